// round 5
// baseline (speedup 1.0000x reference)
#include <cuda_runtime.h>
#include <cuda_bf16.h>
#include <math.h>

#define N_NODES 100000
#define N_EDGES 1600000
#define IN_DIM  256
#define HIDDEN  128
#define OUT_DIM 64
#define E_TOT   (N_EDGES + N_NODES)
#define NEG_SLOPE 0.2f

// ---------------- scratch (static device globals; no allocation) -------------
__device__ float g_h1 [(size_t)N_NODES * HIDDEN];   // x @ W1
__device__ float g_l1 [(size_t)N_NODES * HIDDEN];   // ELU(GAT layer-1 out)
__device__ float g_h2 [(size_t)N_NODES * OUT_DIM];  // l1 @ W2
__device__ float g_ssrc[N_NODES];
__device__ float g_sdst[N_NODES];
__device__ int   g_deg   [N_NODES];
__device__ int   g_rowoff[N_NODES + 1];
__device__ int   g_cursor[N_NODES];
__device__ int   g_csr   [E_TOT];

// ---------------- CSR build --------------------------------------------------
__global__ void k_init_deg() {
    int i = blockIdx.x * blockDim.x + threadIdx.x;
    if (i < N_NODES) g_deg[i] = 1;           // self-loop
}

__global__ void k_hist(const int* __restrict__ ei) {
    int e = blockIdx.x * blockDim.x + threadIdx.x;
    if (e < N_EDGES) atomicAdd(&g_deg[ei[N_EDGES + e]], 1);   // dst row
}

// single-block exclusive scan of g_deg -> g_rowoff / g_cursor
__global__ void k_scan() {
    __shared__ int warp_tot[32];
    __shared__ int chunk_base;
    const int lane = threadIdx.x & 31;
    const int wid  = threadIdx.x >> 5;
    if (threadIdx.x == 0) chunk_base = 0;
    __syncthreads();
    for (int base = 0; base < N_NODES; base += 1024) {
        int i = base + threadIdx.x;
        int v = (i < N_NODES) ? g_deg[i] : 0;
        int x = v;
        #pragma unroll
        for (int o = 1; o < 32; o <<= 1) {
            int t = __shfl_up_sync(0xffffffffu, x, o);
            if (lane >= o) x += t;
        }
        if (lane == 31) warp_tot[wid] = x;
        __syncthreads();
        if (wid == 0) {
            int t = warp_tot[lane];
            #pragma unroll
            for (int o = 1; o < 32; o <<= 1) {
                int u = __shfl_up_sync(0xffffffffu, t, o);
                if (lane >= o) t += u;
            }
            warp_tot[lane] = t;
        }
        __syncthreads();
        int warp_base = (wid == 0) ? 0 : warp_tot[wid - 1];
        int excl = chunk_base + warp_base + x - v;
        if (i < N_NODES) { g_rowoff[i] = excl; g_cursor[i] = excl; }
        __syncthreads();
        if (threadIdx.x == 0) chunk_base += warp_tot[31];
        __syncthreads();
    }
    if (threadIdx.x == 0) g_rowoff[N_NODES] = chunk_base;
}

__global__ void k_scatter(const int* __restrict__ ei) {
    int idx = blockIdx.x * blockDim.x + threadIdx.x;
    if (idx >= E_TOT) return;
    int src, dst;
    if (idx < N_EDGES) { src = ei[idx]; dst = ei[N_EDGES + idx]; }
    else               { src = dst = idx - N_EDGES; }
    int pos = atomicAdd(&g_cursor[dst], 1);
    g_csr[pos] = src;
}

// ---------------- SGEMM (A[MxK] @ B[KxBN] -> C[MxBN]) ------------------------
template <int BN>
__global__ void k_sgemm(int M, int K,
                        const float* __restrict__ A,
                        const float* __restrict__ B,
                        float* __restrict__ C) {
    constexpr int BM = 128, BK = 16, TM = 8, TN = 8;
    constexpr int THREADS = (BM / TM) * (BN / TN);
    __shared__ float As[BK][BM + 4];
    __shared__ float Bs[BK][BN];

    const int tid = threadIdx.x;
    const int tx  = tid % (BN / TN);
    const int ty  = tid / (BN / TN);
    const int rowBase = blockIdx.x * BM;

    float acc[TM][TN];
    #pragma unroll
    for (int m = 0; m < TM; m++)
        #pragma unroll
        for (int n = 0; n < TN; n++) acc[m][n] = 0.f;

    constexpr int A_F4  = BM * BK / 4;
    constexpr int A_PER = A_F4 / THREADS;
    constexpr int B_F4  = BK * BN / 4;
    constexpr int B_PER = B_F4 / THREADS;

    for (int k0 = 0; k0 < K; k0 += BK) {
        #pragma unroll
        for (int i = 0; i < A_PER; i++) {
            int f  = tid + i * THREADS;
            int ar = f >> 2;
            int ac = (f & 3) * 4;
            int gr = rowBase + ar;
            float4 v = make_float4(0.f, 0.f, 0.f, 0.f);
            if (gr < M) v = *(const float4*)&A[(size_t)gr * K + k0 + ac];
            As[ac + 0][ar] = v.x; As[ac + 1][ar] = v.y;
            As[ac + 2][ar] = v.z; As[ac + 3][ar] = v.w;
        }
        #pragma unroll
        for (int i = 0; i < B_PER; i++) {
            int f  = tid + i * THREADS;
            int br = f / (BN / 4);
            int bc = (f % (BN / 4)) * 4;
            *(float4*)&Bs[br][bc] = *(const float4*)&B[(size_t)(k0 + br) * BN + bc];
        }
        __syncthreads();
        #pragma unroll
        for (int k = 0; k < BK; k++) {
            float rm[TM], rn[TN];
            #pragma unroll
            for (int m = 0; m < TM; m++) rm[m] = As[k][ty * TM + m];
            #pragma unroll
            for (int n = 0; n < TN; n++) rn[n] = Bs[k][tx * TN + n];
            #pragma unroll
            for (int m = 0; m < TM; m++)
                #pragma unroll
                for (int n = 0; n < TN; n++) acc[m][n] = fmaf(rm[m], rn[n], acc[m][n]);
        }
        __syncthreads();
    }
    #pragma unroll
    for (int m = 0; m < TM; m++) {
        int gr = rowBase + ty * TM + m;
        if (gr < M) {
            float4 v0 = make_float4(acc[m][0], acc[m][1], acc[m][2], acc[m][3]);
            float4 v1 = make_float4(acc[m][4], acc[m][5], acc[m][6], acc[m][7]);
            *(float4*)&C[(size_t)gr * BN + tx * TN + 0] = v0;
            *(float4*)&C[(size_t)gr * BN + tx * TN + 4] = v1;
        }
    }
}

// ---------------- per-row attention dots -------------------------------------
template <int F>
__global__ void k_rowdots(const float* __restrict__ h,
                          const float* __restrict__ a_src,
                          const float* __restrict__ a_dst) {
    int warp = (blockIdx.x * blockDim.x + threadIdx.x) >> 5;
    int lane = threadIdx.x & 31;
    if (warp >= N_NODES) return;
    float ps = 0.f, pd = 0.f;
    if (F == 128) {
        float4 hv = ((const float4*)h)[(size_t)warp * 32 + lane];
        float4 as = ((const float4*)a_src)[lane];
        float4 ad = ((const float4*)a_dst)[lane];
        ps = hv.x * as.x + hv.y * as.y + hv.z * as.z + hv.w * as.w;
        pd = hv.x * ad.x + hv.y * ad.y + hv.z * ad.z + hv.w * ad.w;
    } else {
        float2 hv = ((const float2*)h)[(size_t)warp * 32 + lane];
        float2 as = ((const float2*)a_src)[lane];
        float2 ad = ((const float2*)a_dst)[lane];
        ps = hv.x * as.x + hv.y * as.y;
        pd = hv.x * ad.x + hv.y * ad.y;
    }
    #pragma unroll
    for (int o = 16; o > 0; o >>= 1) {
        ps += __shfl_down_sync(0xffffffffu, ps, o);
        pd += __shfl_down_sync(0xffffffffu, pd, o);
    }
    if (lane == 0) { g_ssrc[warp] = ps; g_sdst[warp] = pd; }
}

// ---------------- edge softmax + aggregation (warp per dst node) -------------
__device__ __forceinline__ float edge_w(float s, float sd) {
    float e = s + sd;
    e = (e > 0.f) ? e : NEG_SLOPE * e;
    return __expf(e);     // per-dst max elided: cancels exactly in w/sum(w)
}

__global__ void k_agg128(const float* __restrict__ h,
                         const float* __restrict__ bias,
                         float* __restrict__ out, int do_elu) {
    int node = (blockIdx.x * blockDim.x + threadIdx.x) >> 5;
    int lane = threadIdx.x & 31;
    if (node >= N_NODES) return;
    const float4* h4 = (const float4*)h;
    float sd  = g_sdst[node];
    int beg = g_rowoff[node], end = g_rowoff[node + 1];
    float4 acc = make_float4(0.f, 0.f, 0.f, 0.f);
    float denom = 0.f;
    int j = beg;
    for (; j + 3 < end; j += 4) {
        int s0 = g_csr[j], s1 = g_csr[j+1], s2 = g_csr[j+2], s3 = g_csr[j+3];
        float w0 = edge_w(g_ssrc[s0], sd), w1 = edge_w(g_ssrc[s1], sd);
        float w2 = edge_w(g_ssrc[s2], sd), w3 = edge_w(g_ssrc[s3], sd);
        float4 h0 = h4[(size_t)s0 * 32 + lane];
        float4 h1 = h4[(size_t)s1 * 32 + lane];
        float4 h2 = h4[(size_t)s2 * 32 + lane];
        float4 h3 = h4[(size_t)s3 * 32 + lane];
        denom += (w0 + w1) + (w2 + w3);
        acc.x += w0*h0.x + w1*h1.x + w2*h2.x + w3*h3.x;
        acc.y += w0*h0.y + w1*h1.y + w2*h2.y + w3*h3.y;
        acc.z += w0*h0.z + w1*h1.z + w2*h2.z + w3*h3.z;
        acc.w += w0*h0.w + w1*h1.w + w2*h2.w + w3*h3.w;
    }
    for (; j < end; j++) {
        int s = g_csr[j];
        float w = edge_w(g_ssrc[s], sd);
        float4 hv = h4[(size_t)s * 32 + lane];
        denom += w;
        acc.x += w*hv.x; acc.y += w*hv.y; acc.z += w*hv.z; acc.w += w*hv.w;
    }
    float inv = 1.f / denom;
    float4 b = ((const float4*)bias)[lane];
    float4 o;
    o.x = acc.x * inv + b.x; o.y = acc.y * inv + b.y;
    o.z = acc.z * inv + b.z; o.w = acc.w * inv + b.w;
    if (do_elu) {
        o.x = (o.x > 0.f) ? o.x : expm1f(o.x);
        o.y = (o.y > 0.f) ? o.y : expm1f(o.y);
        o.z = (o.z > 0.f) ? o.z : expm1f(o.z);
        o.w = (o.w > 0.f) ? o.w : expm1f(o.w);
    }
    ((float4*)out)[(size_t)node * 32 + lane] = o;
}

__global__ void k_agg64(const float* __restrict__ h,
                        const float* __restrict__ bias,
                        float* __restrict__ out) {
    int node = (blockIdx.x * blockDim.x + threadIdx.x) >> 5;
    int lane = threadIdx.x & 31;
    if (node >= N_NODES) return;
    const float2* h2 = (const float2*)h;
    float sd  = g_sdst[node];
    int beg = g_rowoff[node], end = g_rowoff[node + 1];
    float2 acc = make_float2(0.f, 0.f);
    float denom = 0.f;
    int j = beg;
    for (; j + 3 < end; j += 4) {
        int s0 = g_csr[j], s1 = g_csr[j+1], s2 = g_csr[j+2], s3 = g_csr[j+3];
        float w0 = edge_w(g_ssrc[s0], sd), w1 = edge_w(g_ssrc[s1], sd);
        float w2 = edge_w(g_ssrc[s2], sd), w3 = edge_w(g_ssrc[s3], sd);
        float2 h0 = h2[(size_t)s0 * 32 + lane];
        float2 h1 = h2[(size_t)s1 * 32 + lane];
        float2 hh2 = h2[(size_t)s2 * 32 + lane];
        float2 h3 = h2[(size_t)s3 * 32 + lane];
        denom += (w0 + w1) + (w2 + w3);
        acc.x += w0*h0.x + w1*h1.x + w2*hh2.x + w3*h3.x;
        acc.y += w0*h0.y + w1*h1.y + w2*hh2.y + w3*h3.y;
    }
    for (; j < end; j++) {
        int s = g_csr[j];
        float w = edge_w(g_ssrc[s], sd);
        float2 hv = h2[(size_t)s * 32 + lane];
        denom += w;
        acc.x += w*hv.x; acc.y += w*hv.y;
    }
    float inv = 1.f / denom;
    float2 b = ((const float2*)bias)[lane];
    float2 o;
    o.x = acc.x * inv + b.x;
    o.y = acc.y * inv + b.y;
    ((float2*)out)[(size_t)node * 32 + lane] = o;
}

// ---------------- launch -----------------------------------------------------
extern "C" void kernel_launch(void* const* d_in, const int* in_sizes, int n_in,
                              void* d_out, int out_size) {
    const float* x      = (const float*)d_in[0];
    const int*   ei     = (const int*)  d_in[1];
    const float* W1     = (const float*)d_in[2];
    const float* a1_src = (const float*)d_in[3];
    const float* a1_dst = (const float*)d_in[4];
    const float* b1     = (const float*)d_in[5];
    const float* W2     = (const float*)d_in[6];
    const float* a2_src = (const float*)d_in[7];
    const float* a2_dst = (const float*)d_in[8];
    const float* b2     = (const float*)d_in[9];
    float* out = (float*)d_out;

    float *p_h1, *p_l1, *p_h2;
    cudaGetSymbolAddress((void**)&p_h1, g_h1);
    cudaGetSymbolAddress((void**)&p_l1, g_l1);
    cudaGetSymbolAddress((void**)&p_h2, g_h2);

    // CSR build (shared by both layers)
    k_init_deg<<<(N_NODES + 255) / 256, 256>>>();
    k_hist<<<(N_EDGES + 255) / 256, 256>>>(ei);
    k_scan<<<1, 1024>>>();
    k_scatter<<<(E_TOT + 255) / 256, 256>>>(ei);

    // Layer 1
    k_sgemm<HIDDEN><<<(N_NODES + 127) / 128, 256>>>(N_NODES, IN_DIM, x, W1, p_h1);
    k_rowdots<HIDDEN><<<(N_NODES * 32 + 255) / 256, 256>>>(p_h1, a1_src, a1_dst);
    k_agg128<<<(N_NODES * 32 + 255) / 256, 256>>>(p_h1, b1, p_l1, 1);

    // Layer 2
    k_sgemm<OUT_DIM><<<(N_NODES + 127) / 128, 128>>>(N_NODES, HIDDEN, p_l1, W2, p_h2);
    k_rowdots<OUT_DIM><<<(N_NODES * 32 + 255) / 256, 256>>>(p_h2, a2_src, a2_dst);
    k_agg64<<<(N_NODES * 32 + 255) / 256, 256>>>(p_h2, b2, out);
}

// round 6
// speedup vs baseline: 1.4669x; 1.4669x over previous
#include <cuda_runtime.h>
#include <cuda_bf16.h>
#include <math.h>
#include <stdint.h>

#define N_NODES 100000
#define N_EDGES 1600000
#define IN_DIM  256
#define HIDDEN  128
#define OUT_DIM 64
#define E_TOT   (N_EDGES + N_NODES)
#define NEG_SLOPE 0.2f
#define SCAN_BLK 1024
#define N_SCANB  ((N_NODES + SCAN_BLK - 1) / SCAN_BLK)   // 98

// ---------------- scratch (static device globals; no allocation) -------------
__device__ float g_h1 [(size_t)N_NODES * HIDDEN];
__device__ float g_l1 [(size_t)N_NODES * HIDDEN];
__device__ float g_h2 [(size_t)N_NODES * OUT_DIM];
__device__ float g_ssrc[N_NODES];
__device__ float g_sdst[N_NODES];
__device__ int   g_deg   [N_NODES];
__device__ int   g_rowoff[N_NODES + 1];
__device__ int   g_cursor[N_NODES];
__device__ int   g_csr   [E_TOT];
__device__ int   g_bsum  [128];
__device__ int   g_bpre  [128];

// ---------------- CSR build --------------------------------------------------
__global__ void k_init_deg() {
    int i = blockIdx.x * blockDim.x + threadIdx.x;
    if (i < N_NODES) g_deg[i] = 1;           // self-loop
}

__global__ void k_hist(const int* __restrict__ ei) {
    int e = blockIdx.x * blockDim.x + threadIdx.x;
    if (e < N_EDGES) atomicAdd(&g_deg[ei[N_EDGES + e]], 1);
}

// pass 1: per-block (1024-wide) exclusive scan; block totals to g_bsum
__global__ void k_scan1() {
    __shared__ int wt[32];
    int i = blockIdx.x * SCAN_BLK + threadIdx.x;
    int lane = threadIdx.x & 31, wid = threadIdx.x >> 5;
    int v = (i < N_NODES) ? g_deg[i] : 0;
    int x = v;
    #pragma unroll
    for (int o = 1; o < 32; o <<= 1) {
        int t = __shfl_up_sync(0xffffffffu, x, o);
        if (lane >= o) x += t;
    }
    if (lane == 31) wt[wid] = x;
    __syncthreads();
    if (wid == 0) {
        int t = wt[lane];
        #pragma unroll
        for (int o = 1; o < 32; o <<= 1) {
            int u = __shfl_up_sync(0xffffffffu, t, o);
            if (lane >= o) t += u;
        }
        wt[lane] = t;
    }
    __syncthreads();
    int base = wid ? wt[wid - 1] : 0;
    if (i < N_NODES) g_rowoff[i] = base + x - v;
    if (threadIdx.x == 0) g_bsum[blockIdx.x] = wt[31];
}

// pass 2: single block scans the <=128 block sums
__global__ void k_scan2(int nb) {
    __shared__ int wt[4];
    int lane = threadIdx.x & 31, wid = threadIdx.x >> 5;
    int v = (threadIdx.x < nb) ? g_bsum[threadIdx.x] : 0;
    int x = v;
    #pragma unroll
    for (int o = 1; o < 32; o <<= 1) {
        int t = __shfl_up_sync(0xffffffffu, x, o);
        if (lane >= o) x += t;
    }
    if (lane == 31) wt[wid] = x;
    __syncthreads();
    if (threadIdx.x == 0) {
        int s = 0;
        #pragma unroll
        for (int w = 0; w < 4; w++) { int t = wt[w]; wt[w] = s; s += t; }
        g_rowoff[N_NODES] = s;
    }
    __syncthreads();
    if (threadIdx.x < nb) g_bpre[threadIdx.x] = wt[wid] + x - v;
}

// pass 3: add block prefixes, init cursor
__global__ void k_scan3() {
    int i = blockIdx.x * blockDim.x + threadIdx.x;
    if (i >= N_NODES) return;
    int r = g_rowoff[i] + g_bpre[i / SCAN_BLK];
    g_rowoff[i] = r;
    g_cursor[i] = r;
}

__global__ void k_scatter(const int* __restrict__ ei) {
    int idx = blockIdx.x * blockDim.x + threadIdx.x;
    if (idx >= E_TOT) return;
    int src, dst;
    if (idx < N_EDGES) { src = ei[idx]; dst = ei[N_EDGES + idx]; }
    else               { src = dst = idx - N_EDGES; }
    int pos = atomicAdd(&g_cursor[dst], 1);
    g_csr[pos] = src;
}

// ---------------- TF32 tensor-core GEMM (A[MxK] @ B[KxBN] -> C[MxBN]) --------
__device__ __forceinline__ uint32_t f2tf32(float f) {
    uint32_t r;
    asm("cvt.rna.tf32.f32 %0, %1;" : "=r"(r) : "f"(f));
    return r;
}

__device__ __forceinline__ void mma_tf32(float c[4], const uint32_t a[4], const uint32_t b[2]) {
    asm volatile(
        "mma.sync.aligned.m16n8k8.row.col.f32.tf32.tf32.f32 "
        "{%0,%1,%2,%3}, {%4,%5,%6,%7}, {%8,%9}, {%0,%1,%2,%3};"
        : "+f"(c[0]), "+f"(c[1]), "+f"(c[2]), "+f"(c[3])
        : "r"(a[0]), "r"(a[1]), "r"(a[2]), "r"(a[3]), "r"(b[0]), "r"(b[1]));
}

template <int BN>
__global__ void k_mm(int M, int K,
                     const float* __restrict__ A,
                     const float* __restrict__ B,
                     float* __restrict__ C) {
    constexpr int BM = 128, BK = 32;
    constexpr int WM = 64, WN = 32;
    constexpr int WARPS_M = BM / WM;           // 2
    constexpr int WARPS_N = BN / WN;           // 4 or 2
    constexpr int THREADS = WARPS_M * WARPS_N * 32;
    __shared__ uint32_t As[BK][BM + 8];
    __shared__ uint32_t Bs[BK][BN + 8];

    const int tid  = threadIdx.x;
    const int lane = tid & 31;
    const int warp = tid >> 5;
    const int wm = warp % WARPS_M;
    const int wn = warp / WARPS_M;
    const int g  = lane >> 2;
    const int tg = lane & 3;
    const int rowBase = blockIdx.x * BM;

    float c[4][4][4];                           // [mtile][ntile][frag]
    #pragma unroll
    for (int i = 0; i < 4; i++)
        #pragma unroll
        for (int j = 0; j < 4; j++)
            #pragma unroll
            for (int q = 0; q < 4; q++) c[i][j][q] = 0.f;

    constexpr int A_F4  = BM * BK / 4;          // 1024
    constexpr int A_PER = A_F4 / THREADS;
    constexpr int B_F4  = BK * BN / 4;
    constexpr int B_PER = B_F4 / THREADS;

    for (int k0 = 0; k0 < K; k0 += BK) {
        // A tile -> As (transposed, tf32-converted)
        #pragma unroll
        for (int i = 0; i < A_PER; i++) {
            int f  = tid + i * THREADS;
            int ar = f >> 3;                    // BK/4 = 8 float4 per row
            int ac = (f & 7) * 4;
            int gr = rowBase + ar;
            float4 v = make_float4(0.f, 0.f, 0.f, 0.f);
            if (gr < M) v = *(const float4*)&A[(size_t)gr * K + k0 + ac];
            As[ac + 0][ar] = f2tf32(v.x);
            As[ac + 1][ar] = f2tf32(v.y);
            As[ac + 2][ar] = f2tf32(v.z);
            As[ac + 3][ar] = f2tf32(v.w);
        }
        // B tile -> Bs (tf32-converted)
        #pragma unroll
        for (int i = 0; i < B_PER; i++) {
            int f  = tid + i * THREADS;
            int br = f / (BN / 4);
            int bc = (f % (BN / 4)) * 4;
            float4 v = *(const float4*)&B[(size_t)(k0 + br) * BN + bc];
            uint4 u;
            u.x = f2tf32(v.x); u.y = f2tf32(v.y);
            u.z = f2tf32(v.z); u.w = f2tf32(v.w);
            *(uint4*)&Bs[br][bc] = u;
        }
        __syncthreads();

        #pragma unroll
        for (int kk = 0; kk < BK; kk += 8) {
            uint32_t a[4][4], b[4][2];
            #pragma unroll
            for (int mt = 0; mt < 4; mt++) {
                int r = wm * WM + mt * 16;
                a[mt][0] = As[kk + tg    ][r + g    ];
                a[mt][1] = As[kk + tg    ][r + g + 8];
                a[mt][2] = As[kk + tg + 4][r + g    ];
                a[mt][3] = As[kk + tg + 4][r + g + 8];
            }
            #pragma unroll
            for (int nt = 0; nt < 4; nt++) {
                int cn = wn * WN + nt * 8 + g;
                b[nt][0] = Bs[kk + tg    ][cn];
                b[nt][1] = Bs[kk + tg + 4][cn];
            }
            #pragma unroll
            for (int mt = 0; mt < 4; mt++)
                #pragma unroll
                for (int nt = 0; nt < 4; nt++)
                    mma_tf32(c[mt][nt], a[mt], b[nt]);
        }
        __syncthreads();
    }

    // epilogue
    #pragma unroll
    for (int mt = 0; mt < 4; mt++) {
        int r0 = rowBase + wm * WM + mt * 16 + g;
        #pragma unroll
        for (int nt = 0; nt < 4; nt++) {
            int cc = wn * WN + nt * 8 + tg * 2;
            if (r0 < M)
                *(float2*)&C[(size_t)r0 * BN + cc] = make_float2(c[mt][nt][0], c[mt][nt][1]);
            if (r0 + 8 < M)
                *(float2*)&C[(size_t)(r0 + 8) * BN + cc] = make_float2(c[mt][nt][2], c[mt][nt][3]);
        }
    }
}

// ---------------- per-row attention dots -------------------------------------
template <int F>
__global__ void k_rowdots(const float* __restrict__ h,
                          const float* __restrict__ a_src,
                          const float* __restrict__ a_dst) {
    int warp = (blockIdx.x * blockDim.x + threadIdx.x) >> 5;
    int lane = threadIdx.x & 31;
    if (warp >= N_NODES) return;
    float ps = 0.f, pd = 0.f;
    if (F == 128) {
        float4 hv = ((const float4*)h)[(size_t)warp * 32 + lane];
        float4 as = ((const float4*)a_src)[lane];
        float4 ad = ((const float4*)a_dst)[lane];
        ps = hv.x * as.x + hv.y * as.y + hv.z * as.z + hv.w * as.w;
        pd = hv.x * ad.x + hv.y * ad.y + hv.z * ad.z + hv.w * ad.w;
    } else {
        float2 hv = ((const float2*)h)[(size_t)warp * 32 + lane];
        float2 as = ((const float2*)a_src)[lane];
        float2 ad = ((const float2*)a_dst)[lane];
        ps = hv.x * as.x + hv.y * as.y;
        pd = hv.x * ad.x + hv.y * ad.y;
    }
    #pragma unroll
    for (int o = 16; o > 0; o >>= 1) {
        ps += __shfl_down_sync(0xffffffffu, ps, o);
        pd += __shfl_down_sync(0xffffffffu, pd, o);
    }
    if (lane == 0) { g_ssrc[warp] = ps; g_sdst[warp] = pd; }
}

// ---------------- edge softmax + aggregation (warp per dst node) -------------
__device__ __forceinline__ float edge_w(float s, float sd) {
    float e = s + sd;
    e = (e > 0.f) ? e : NEG_SLOPE * e;
    return __expf(e);     // per-dst max elided: cancels exactly in w/sum(w)
}

__global__ void k_agg128(const float* __restrict__ h,
                         const float* __restrict__ bias,
                         float* __restrict__ out, int do_elu) {
    int node = (blockIdx.x * blockDim.x + threadIdx.x) >> 5;
    int lane = threadIdx.x & 31;
    if (node >= N_NODES) return;
    const float4* h4 = (const float4*)h;
    float sd  = g_sdst[node];
    int beg = g_rowoff[node], end = g_rowoff[node + 1];
    float4 acc = make_float4(0.f, 0.f, 0.f, 0.f);
    float denom = 0.f;
    int j = beg;
    for (; j + 3 < end; j += 4) {
        int s0 = g_csr[j], s1 = g_csr[j+1], s2 = g_csr[j+2], s3 = g_csr[j+3];
        float w0 = edge_w(g_ssrc[s0], sd), w1 = edge_w(g_ssrc[s1], sd);
        float w2 = edge_w(g_ssrc[s2], sd), w3 = edge_w(g_ssrc[s3], sd);
        float4 h0 = h4[(size_t)s0 * 32 + lane];
        float4 h1 = h4[(size_t)s1 * 32 + lane];
        float4 h2 = h4[(size_t)s2 * 32 + lane];
        float4 h3 = h4[(size_t)s3 * 32 + lane];
        denom += (w0 + w1) + (w2 + w3);
        acc.x += w0*h0.x + w1*h1.x + w2*h2.x + w3*h3.x;
        acc.y += w0*h0.y + w1*h1.y + w2*h2.y + w3*h3.y;
        acc.z += w0*h0.z + w1*h1.z + w2*h2.z + w3*h3.z;
        acc.w += w0*h0.w + w1*h1.w + w2*h2.w + w3*h3.w;
    }
    for (; j < end; j++) {
        int s = g_csr[j];
        float w = edge_w(g_ssrc[s], sd);
        float4 hv = h4[(size_t)s * 32 + lane];
        denom += w;
        acc.x += w*hv.x; acc.y += w*hv.y; acc.z += w*hv.z; acc.w += w*hv.w;
    }
    float inv = 1.f / denom;
    float4 b = ((const float4*)bias)[lane];
    float4 o;
    o.x = acc.x * inv + b.x; o.y = acc.y * inv + b.y;
    o.z = acc.z * inv + b.z; o.w = acc.w * inv + b.w;
    if (do_elu) {
        o.x = (o.x > 0.f) ? o.x : expm1f(o.x);
        o.y = (o.y > 0.f) ? o.y : expm1f(o.y);
        o.z = (o.z > 0.f) ? o.z : expm1f(o.z);
        o.w = (o.w > 0.f) ? o.w : expm1f(o.w);
    }
    ((float4*)out)[(size_t)node * 32 + lane] = o;
}

__global__ void k_agg64(const float* __restrict__ h,
                        const float* __restrict__ bias,
                        float* __restrict__ out) {
    int node = (blockIdx.x * blockDim.x + threadIdx.x) >> 5;
    int lane = threadIdx.x & 31;
    if (node >= N_NODES) return;
    const float2* h2 = (const float2*)h;
    float sd  = g_sdst[node];
    int beg = g_rowoff[node], end = g_rowoff[node + 1];
    float2 acc = make_float2(0.f, 0.f);
    float denom = 0.f;
    int j = beg;
    for (; j + 3 < end; j += 4) {
        int s0 = g_csr[j], s1 = g_csr[j+1], s2 = g_csr[j+2], s3 = g_csr[j+3];
        float w0 = edge_w(g_ssrc[s0], sd), w1 = edge_w(g_ssrc[s1], sd);
        float w2 = edge_w(g_ssrc[s2], sd), w3 = edge_w(g_ssrc[s3], sd);
        float2 h0 = h2[(size_t)s0 * 32 + lane];
        float2 h1 = h2[(size_t)s1 * 32 + lane];
        float2 hh2 = h2[(size_t)s2 * 32 + lane];
        float2 h3 = h2[(size_t)s3 * 32 + lane];
        denom += (w0 + w1) + (w2 + w3);
        acc.x += w0*h0.x + w1*h1.x + w2*hh2.x + w3*h3.x;
        acc.y += w0*h0.y + w1*h1.y + w2*hh2.y + w3*h3.y;
    }
    for (; j < end; j++) {
        int s = g_csr[j];
        float w = edge_w(g_ssrc[s], sd);
        float2 hv = h2[(size_t)s * 32 + lane];
        denom += w;
        acc.x += w*hv.x; acc.y += w*hv.y;
    }
    float inv = 1.f / denom;
    float2 b = ((const float2*)bias)[lane];
    float2 o;
    o.x = acc.x * inv + b.x;
    o.y = acc.y * inv + b.y;
    ((float2*)out)[(size_t)node * 32 + lane] = o;
}

// ---------------- launch -----------------------------------------------------
extern "C" void kernel_launch(void* const* d_in, const int* in_sizes, int n_in,
                              void* d_out, int out_size) {
    const float* x      = (const float*)d_in[0];
    const int*   ei     = (const int*)  d_in[1];
    const float* W1     = (const float*)d_in[2];
    const float* a1_src = (const float*)d_in[3];
    const float* a1_dst = (const float*)d_in[4];
    const float* b1     = (const float*)d_in[5];
    const float* W2     = (const float*)d_in[6];
    const float* a2_src = (const float*)d_in[7];
    const float* a2_dst = (const float*)d_in[8];
    const float* b2     = (const float*)d_in[9];
    float* out = (float*)d_out;

    float *p_h1, *p_l1, *p_h2;
    cudaGetSymbolAddress((void**)&p_h1, g_h1);
    cudaGetSymbolAddress((void**)&p_l1, g_l1);
    cudaGetSymbolAddress((void**)&p_h2, g_h2);

    // CSR build (shared by both layers)
    k_init_deg<<<(N_NODES + 255) / 256, 256>>>();
    k_hist<<<(N_EDGES + 255) / 256, 256>>>(ei);
    k_scan1<<<N_SCANB, SCAN_BLK>>>();
    k_scan2<<<1, 128>>>(N_SCANB);
    k_scan3<<<(N_NODES + 255) / 256, 256>>>();
    k_scatter<<<(E_TOT + 255) / 256, 256>>>(ei);

    // Layer 1
    k_mm<HIDDEN><<<(N_NODES + 127) / 128, 256>>>(N_NODES, IN_DIM, x, W1, p_h1);
    k_rowdots<HIDDEN><<<(N_NODES * 32 + 255) / 256, 256>>>(p_h1, a1_src, a1_dst);
    k_agg128<<<(N_NODES * 32 + 255) / 256, 256>>>(p_h1, b1, p_l1, 1);

    // Layer 2
    k_mm<OUT_DIM><<<(N_NODES + 127) / 128, 128>>>(N_NODES, HIDDEN, p_l1, W2, p_h2);
    k_rowdots<OUT_DIM><<<(N_NODES * 32 + 255) / 256, 256>>>(p_h2, a2_src, a2_dst);
    k_agg64<<<(N_NODES * 32 + 255) / 256, 256>>>(p_h2, b2, out);
}

// round 12
// speedup vs baseline: 1.4711x; 1.0029x over previous
#include <cuda_runtime.h>
#include <cuda_bf16.h>
#include <math.h>
#include <stdint.h>

#define N_NODES 100000
#define N_EDGES 1600000
#define IN_DIM  256
#define HIDDEN  128
#define OUT_DIM 64
#define E_TOT   (N_EDGES + N_NODES)
#define NEG_SLOPE 0.2f
#define SCAN_BLK 1024
#define N_SCANB  ((N_NODES + SCAN_BLK - 1) / SCAN_BLK)   // 98

// ---------------- scratch (static device globals; no allocation) -------------
__device__ float g_h1 [(size_t)N_NODES * HIDDEN];
__device__ float g_l1 [(size_t)N_NODES * HIDDEN];
__device__ float g_h2 [(size_t)N_NODES * OUT_DIM];
__device__ float g_ssrc[N_NODES];
__device__ float g_sdst[N_NODES];
__device__ int   g_deg   [N_NODES];
__device__ int   g_rowoff[N_NODES + 1];
__device__ int   g_cursor[N_NODES];
__device__ int   g_csr   [E_TOT];
__device__ int   g_bsum  [128];
__device__ int   g_bpre  [128];

// ---------------- CSR build --------------------------------------------------
__global__ void k_hist(const int* __restrict__ ei) {
    int e = blockIdx.x * blockDim.x + threadIdx.x;
    if (e < N_EDGES) atomicAdd(&g_deg[ei[N_EDGES + e]], 1);
}

// pass 1: per-block exclusive scan of (deg+1); block totals to g_bsum
__global__ void k_scan1() {
    __shared__ int wt[32];
    int i = blockIdx.x * SCAN_BLK + threadIdx.x;
    int lane = threadIdx.x & 31, wid = threadIdx.x >> 5;
    int v = (i < N_NODES) ? (g_deg[i] + 1) : 0;    // +1 = self loop
    int x = v;
    #pragma unroll
    for (int o = 1; o < 32; o <<= 1) {
        int t = __shfl_up_sync(0xffffffffu, x, o);
        if (lane >= o) x += t;
    }
    if (lane == 31) wt[wid] = x;
    __syncthreads();
    if (wid == 0) {
        int t = wt[lane];
        #pragma unroll
        for (int o = 1; o < 32; o <<= 1) {
            int u = __shfl_up_sync(0xffffffffu, t, o);
            if (lane >= o) t += u;
        }
        wt[lane] = t;
    }
    __syncthreads();
    int base = wid ? wt[wid - 1] : 0;
    if (i < N_NODES) g_rowoff[i] = base + x - v;
    if (threadIdx.x == 0) g_bsum[blockIdx.x] = wt[31];
}

__global__ void k_scan2(int nb) {
    __shared__ int wt[4];
    int lane = threadIdx.x & 31, wid = threadIdx.x >> 5;
    int v = (threadIdx.x < nb) ? g_bsum[threadIdx.x] : 0;
    int x = v;
    #pragma unroll
    for (int o = 1; o < 32; o <<= 1) {
        int t = __shfl_up_sync(0xffffffffu, x, o);
        if (lane >= o) x += t;
    }
    if (lane == 31) wt[wid] = x;
    __syncthreads();
    if (threadIdx.x == 0) {
        int s = 0;
        #pragma unroll
        for (int w = 0; w < 4; w++) { int t = wt[w]; wt[w] = s; s += t; }
        g_rowoff[N_NODES] = s;
    }
    __syncthreads();
    if (threadIdx.x < nb) g_bpre[threadIdx.x] = wt[wid] + x - v;
}

__global__ void k_scan3() {
    int i = blockIdx.x * blockDim.x + threadIdx.x;
    if (i >= N_NODES) return;
    int r = g_rowoff[i] + g_bpre[i / SCAN_BLK];
    g_rowoff[i] = r;
    g_cursor[i] = r;
}

__global__ void k_scatter(const int* __restrict__ ei) {
    int idx = blockIdx.x * blockDim.x + threadIdx.x;
    if (idx >= E_TOT) return;
    int src, dst;
    if (idx < N_EDGES) { src = ei[idx]; dst = ei[N_EDGES + idx]; }
    else               { src = dst = idx - N_EDGES; }
    int pos = atomicAdd(&g_cursor[dst], 1);
    g_csr[pos] = src;
}

// ---------------- TF32 tensor-core GEMM + fused attention dots ---------------
__device__ __forceinline__ uint32_t f2tf32(float f) {
    uint32_t r;
    asm("cvt.rna.tf32.f32 %0, %1;" : "=r"(r) : "f"(f));
    return r;
}

__device__ __forceinline__ void mma_tf32(float c[4], const uint32_t a[4], const uint32_t b[2]) {
    asm volatile(
        "mma.sync.aligned.m16n8k8.row.col.f32.tf32.tf32.f32 "
        "{%0,%1,%2,%3}, {%4,%5,%6,%7}, {%8,%9}, {%0,%1,%2,%3};"
        : "+f"(c[0]), "+f"(c[1]), "+f"(c[2]), "+f"(c[3])
        : "r"(a[0]), "r"(a[1]), "r"(a[2]), "r"(a[3]), "r"(b[0]), "r"(b[1]));
}

// C[MxBN] = A[MxK] @ B[KxBN]; also writes g_ssrc/g_sdst = C @ a_src / C @ a_dst
template <int BN>
__global__ void k_mm(int M, int K,
                     const float* __restrict__ A,
                     const float* __restrict__ B,
                     float* __restrict__ C,
                     const float* __restrict__ a_src,
                     const float* __restrict__ a_dst) {
    constexpr int BM = 128, BK = 32;
    constexpr int WM = 64, WN = 32;
    constexpr int WARPS_M = BM / WM;           // 2
    constexpr int WARPS_N = BN / WN;           // 4 (BN=128) or 2 (BN=64)
    constexpr int THREADS = WARPS_M * WARPS_N * 32;
    __shared__ uint32_t As[BK][BM + 8];
    __shared__ uint32_t Bs[BK][BN + 8];
    __shared__ float s_ps[WARPS_N][BM];
    __shared__ float s_pd[WARPS_N][BM];

    const int tid  = threadIdx.x;
    const int lane = tid & 31;
    const int warp = tid >> 5;
    const int wm = warp % WARPS_M;
    const int wn = warp / WARPS_M;
    const int g  = lane >> 2;
    const int tg = lane & 3;
    const int rowBase = blockIdx.x * BM;

    // [mtile (WM/16=4)][ntile (WN/8=4, ALWAYS 4)][frag]
    float c[4][4][4];
    #pragma unroll
    for (int i = 0; i < 4; i++)
        #pragma unroll
        for (int j = 0; j < 4; j++)
            #pragma unroll
            for (int q = 0; q < 4; q++) c[i][j][q] = 0.f;

    constexpr int A_F4  = BM * BK / 4;
    constexpr int A_PER = A_F4 / THREADS;
    constexpr int B_F4  = BK * BN / 4;
    constexpr int B_PER = B_F4 / THREADS;

    for (int k0 = 0; k0 < K; k0 += BK) {
        #pragma unroll
        for (int i = 0; i < A_PER; i++) {
            int f  = tid + i * THREADS;
            int ar = f >> 3;
            int ac = (f & 7) * 4;
            int gr = rowBase + ar;
            float4 v = make_float4(0.f, 0.f, 0.f, 0.f);
            if (gr < M) v = *(const float4*)&A[(size_t)gr * K + k0 + ac];
            As[ac + 0][ar] = f2tf32(v.x);
            As[ac + 1][ar] = f2tf32(v.y);
            As[ac + 2][ar] = f2tf32(v.z);
            As[ac + 3][ar] = f2tf32(v.w);
        }
        #pragma unroll
        for (int i = 0; i < B_PER; i++) {
            int f  = tid + i * THREADS;
            int br = f / (BN / 4);
            int bc = (f % (BN / 4)) * 4;
            float4 v = *(const float4*)&B[(size_t)(k0 + br) * BN + bc];
            uint4 u;
            u.x = f2tf32(v.x); u.y = f2tf32(v.y);
            u.z = f2tf32(v.z); u.w = f2tf32(v.w);
            *(uint4*)&Bs[br][bc] = u;
        }
        __syncthreads();

        #pragma unroll
        for (int kk = 0; kk < BK; kk += 8) {
            uint32_t a[4][4], b[4][2];
            #pragma unroll
            for (int mt = 0; mt < 4; mt++) {
                int r = wm * WM + mt * 16;
                a[mt][0] = As[kk + tg    ][r + g    ];
                a[mt][1] = As[kk + tg    ][r + g + 8];
                a[mt][2] = As[kk + tg + 4][r + g    ];
                a[mt][3] = As[kk + tg + 4][r + g + 8];
            }
            #pragma unroll
            for (int nt = 0; nt < 4; nt++) {
                int cn = wn * WN + nt * 8 + g;
                b[nt][0] = Bs[kk + tg    ][cn];
                b[nt][1] = Bs[kk + tg + 4][cn];
            }
            #pragma unroll
            for (int mt = 0; mt < 4; mt++)
                #pragma unroll
                for (int nt = 0; nt < 4; nt++)
                    mma_tf32(c[mt][nt], a[mt], b[nt]);
        }
        __syncthreads();
    }

    // ---- epilogue: store C + fused attention dots ----
    float ps[4][2], pd[4][2];
    #pragma unroll
    for (int mt = 0; mt < 4; mt++) { ps[mt][0]=ps[mt][1]=pd[mt][0]=pd[mt][1]=0.f; }

    #pragma unroll
    for (int mt = 0; mt < 4; mt++) {
        int r0 = rowBase + wm * WM + mt * 16 + g;
        #pragma unroll
        for (int nt = 0; nt < 4; nt++) {
            int cc = wn * WN + nt * 8 + tg * 2;
            float as0 = a_src[cc], as1 = a_src[cc + 1];
            float ad0 = a_dst[cc], ad1 = a_dst[cc + 1];
            ps[mt][0] += c[mt][nt][0] * as0 + c[mt][nt][1] * as1;
            pd[mt][0] += c[mt][nt][0] * ad0 + c[mt][nt][1] * ad1;
            ps[mt][1] += c[mt][nt][2] * as0 + c[mt][nt][3] * as1;
            pd[mt][1] += c[mt][nt][2] * ad0 + c[mt][nt][3] * ad1;
            if (r0 < M)
                *(float2*)&C[(size_t)r0 * BN + cc] = make_float2(c[mt][nt][0], c[mt][nt][1]);
            if (r0 + 8 < M)
                *(float2*)&C[(size_t)(r0 + 8) * BN + cc] = make_float2(c[mt][nt][2], c[mt][nt][3]);
        }
    }
    // reduce over tg (lane bits 0..1) — deterministic butterfly
    #pragma unroll
    for (int mt = 0; mt < 4; mt++)
        #pragma unroll
        for (int hf = 0; hf < 2; hf++) {
            float vs = ps[mt][hf], vd = pd[mt][hf];
            vs += __shfl_xor_sync(0xffffffffu, vs, 1);
            vs += __shfl_xor_sync(0xffffffffu, vs, 2);
            vd += __shfl_xor_sync(0xffffffffu, vd, 1);
            vd += __shfl_xor_sync(0xffffffffu, vd, 2);
            if (tg == 0) {
                int rl = wm * WM + mt * 16 + hf * 8 + g;
                s_ps[wn][rl] = vs;
                s_pd[wn][rl] = vd;
            }
        }
    __syncthreads();
    if (tid < BM) {
        float ts = 0.f, td = 0.f;
        #pragma unroll
        for (int w = 0; w < WARPS_N; w++) { ts += s_ps[w][tid]; td += s_pd[w][tid]; }
        int gr = rowBase + tid;
        if (gr < M) { g_ssrc[gr] = ts; g_sdst[gr] = td; }
    }
}

// ---------------- edge softmax + aggregation (warp per dst node) -------------
__device__ __forceinline__ float edge_w(float s, float sd) {
    float e = s + sd;
    e = (e > 0.f) ? e : NEG_SLOPE * e;
    return __expf(e);     // per-dst max elided: cancels exactly in w/sum(w)
}

__global__ void k_agg128(const float* __restrict__ h,
                         const float* __restrict__ bias,
                         float* __restrict__ out, int do_elu) {
    int node = (blockIdx.x * blockDim.x + threadIdx.x) >> 5;
    int lane = threadIdx.x & 31;
    if (node >= N_NODES) return;
    const float4* h4 = (const float4*)h;
    float sd  = g_sdst[node];
    int beg = g_rowoff[node], end = g_rowoff[node + 1];
    float4 acc = make_float4(0.f, 0.f, 0.f, 0.f);
    float denom = 0.f;
    int j = beg;
    for (; j + 7 < end; j += 8) {
        int s[8];
        #pragma unroll
        for (int u = 0; u < 8; u++) s[u] = g_csr[j + u];
        float sv[8];
        #pragma unroll
        for (int u = 0; u < 8; u++) sv[u] = g_ssrc[s[u]];
        float4 hv[8];
        #pragma unroll
        for (int u = 0; u < 8; u++) hv[u] = h4[(size_t)s[u] * 32 + lane];
        #pragma unroll
        for (int u = 0; u < 8; u++) {
            float w = edge_w(sv[u], sd);
            denom += w;
            acc.x += w * hv[u].x; acc.y += w * hv[u].y;
            acc.z += w * hv[u].z; acc.w += w * hv[u].w;
        }
    }
    for (; j < end; j++) {
        int s = g_csr[j];
        float w = edge_w(g_ssrc[s], sd);
        float4 hv = h4[(size_t)s * 32 + lane];
        denom += w;
        acc.x += w*hv.x; acc.y += w*hv.y; acc.z += w*hv.z; acc.w += w*hv.w;
    }
    float inv = 1.f / denom;
    float4 b = ((const float4*)bias)[lane];
    float4 o;
    o.x = acc.x * inv + b.x; o.y = acc.y * inv + b.y;
    o.z = acc.z * inv + b.z; o.w = acc.w * inv + b.w;
    if (do_elu) {
        o.x = (o.x > 0.f) ? o.x : expm1f(o.x);
        o.y = (o.y > 0.f) ? o.y : expm1f(o.y);
        o.z = (o.z > 0.f) ? o.z : expm1f(o.z);
        o.w = (o.w > 0.f) ? o.w : expm1f(o.w);
    }
    ((float4*)out)[(size_t)node * 32 + lane] = o;
}

__global__ void k_agg64(const float* __restrict__ h,
                        const float* __restrict__ bias,
                        float* __restrict__ out) {
    int node = (blockIdx.x * blockDim.x + threadIdx.x) >> 5;
    int lane = threadIdx.x & 31;
    if (node >= N_NODES) return;
    const float2* h2 = (const float2*)h;
    float sd  = g_sdst[node];
    int beg = g_rowoff[node], end = g_rowoff[node + 1];
    float2 acc = make_float2(0.f, 0.f);
    float denom = 0.f;
    int j = beg;
    for (; j + 7 < end; j += 8) {
        int s[8];
        #pragma unroll
        for (int u = 0; u < 8; u++) s[u] = g_csr[j + u];
        float sv[8];
        #pragma unroll
        for (int u = 0; u < 8; u++) sv[u] = g_ssrc[s[u]];
        float2 hv[8];
        #pragma unroll
        for (int u = 0; u < 8; u++) hv[u] = h2[(size_t)s[u] * 32 + lane];
        #pragma unroll
        for (int u = 0; u < 8; u++) {
            float w = edge_w(sv[u], sd);
            denom += w;
            acc.x += w * hv[u].x; acc.y += w * hv[u].y;
        }
    }
    for (; j < end; j++) {
        int s = g_csr[j];
        float w = edge_w(g_ssrc[s], sd);
        float2 hv = h2[(size_t)s * 32 + lane];
        denom += w;
        acc.x += w*hv.x; acc.y += w*hv.y;
    }
    float inv = 1.f / denom;
    float2 b = ((const float2*)bias)[lane];
    float2 o;
    o.x = acc.x * inv + b.x;
    o.y = acc.y * inv + b.y;
    ((float2*)out)[(size_t)node * 32 + lane] = o;
}

// ---------------- launch -----------------------------------------------------
extern "C" void kernel_launch(void* const* d_in, const int* in_sizes, int n_in,
                              void* d_out, int out_size) {
    const float* x      = (const float*)d_in[0];
    const int*   ei     = (const int*)  d_in[1];
    const float* W1     = (const float*)d_in[2];
    const float* a1_src = (const float*)d_in[3];
    const float* a1_dst = (const float*)d_in[4];
    const float* b1     = (const float*)d_in[5];
    const float* W2     = (const float*)d_in[6];
    const float* a2_src = (const float*)d_in[7];
    const float* a2_dst = (const float*)d_in[8];
    const float* b2     = (const float*)d_in[9];
    float* out = (float*)d_out;

    float *p_h1, *p_l1, *p_h2;
    void *p_deg;
    cudaGetSymbolAddress((void**)&p_h1, g_h1);
    cudaGetSymbolAddress((void**)&p_l1, g_l1);
    cudaGetSymbolAddress((void**)&p_h2, g_h2);
    cudaGetSymbolAddress(&p_deg, g_deg);

    // CSR build (shared by both layers)
    cudaMemsetAsync(p_deg, 0, N_NODES * sizeof(int));
    k_hist<<<(N_EDGES + 255) / 256, 256>>>(ei);
    k_scan1<<<N_SCANB, SCAN_BLK>>>();
    k_scan2<<<1, 128>>>(N_SCANB);
    k_scan3<<<(N_NODES + 255) / 256, 256>>>();
    k_scatter<<<(E_TOT + 255) / 256, 256>>>(ei);

    // Layer 1
    k_mm<HIDDEN><<<(N_NODES + 127) / 128, 256>>>(N_NODES, IN_DIM, x, W1, p_h1, a1_src, a1_dst);
    k_agg128<<<(N_NODES * 32 + 255) / 256, 256>>>(p_h1, b1, p_l1, 1);

    // Layer 2
    k_mm<OUT_DIM><<<(N_NODES + 127) / 128, 128>>>(N_NODES, HIDDEN, p_l1, W2, p_h2, a2_src, a2_dst);
    k_agg64<<<(N_NODES * 32 + 255) / 256, 256>>>(p_h2, b2, out);
}